// round 16
// baseline (speedup 1.0000x reference)
#include <cuda_runtime.h>
#include <cuda_fp16.h>
#include <math.h>

#define NN 50000
#define EE 600000
#define DD 128
#define RR 1000
#define TT 500
#define SCAN_B 256
#define NPART  ((NN + SCAN_B - 1) / SCAN_B)   // 196

// scratch (static device globals — no allocation; zero-initialized at load)
__device__ __half g_h0[NN * DD];                // relu(features), fp16 mirror
__device__ __half g_h1[NN * DD];                // layer-1 features, fp16 mirror
__device__ __half g_hemb[(RR + TT) * DD];       // fp16 mirror of rel|time embeddings
__device__ float g_score[NN];                   // combined edge scores (only first N used)
__device__ float g_p1r[NN], g_p2r[NN], g_p1t[NN], g_p2t[NN];
__device__ float g_nrm[RR + TT];
__device__ float g_u2[2][RR + TT], g_u3[2][RR + TT];
__device__ int   g_cnt[NN];                     // re-zeroed by score_scatter each call
__device__ int   g_rowptr[NN + 1];
__device__ int   g_rank[EE];                    // within-row rank of each edge
__device__ int   g_ecol[EE];                    // acol values in CSR order
__device__ int   g_part[NPART];                 // lookback flags: 0=pending, sum+1=ready

__device__ __forceinline__ float wsum(float v) {
#pragma unroll
    for (int o = 16; o > 0; o >>= 1) v += __shfl_down_sync(0xffffffffu, v, o);
    return v;
}

__device__ __forceinline__ float dot4(float4 a, float4 b) {
    return a.x * b.x + a.y * b.y + a.z * b.z + a.w * b.w;
}

__device__ __forceinline__ uint2 pack_half4(float4 v) {
    __half2 a = __floats2half2_rn(v.x, v.y);
    __half2 b = __floats2half2_rn(v.z, v.w);
    uint2 u;
    u.x = *reinterpret_cast<unsigned*>(&a);
    u.y = *reinterpret_cast<unsigned*>(&b);
    return u;
}

__device__ __forceinline__ float4 unpack_half4(uint2 u) {
    __half2 a = *reinterpret_cast<__half2*>(&u.x);
    __half2 b = *reinterpret_cast<__half2*>(&u.y);
    float2 f1 = __half22float2(a);
    float2 f2 = __half22float2(b);
    return make_float4(f1.x, f1.y, f2.x, f2.y);
}

__device__ __forceinline__ float dot8h(uint4 a, uint4 b) {
    float4 a1 = unpack_half4(make_uint2(a.x, a.y));
    float4 a2 = unpack_half4(make_uint2(a.z, a.w));
    float4 b1 = unpack_half4(make_uint2(b.x, b.y));
    float4 b2 = unpack_half4(make_uint2(b.z, b.w));
    return dot4(a1, b1) + dot4(a2, b2);
}

// packed f32x2 FMA: acc = a * b + acc   (2 fp32 lanes in one instruction)
#define FMA_F32X2(acc, a, b) \
    asm("fma.rn.f32x2 %0, %1, %2, %0;" : "+l"(acc) : "l"(a), "l"(b))

__device__ __forceinline__ unsigned long long pack_f32x2(float lo, float hi) {
    unsigned long long u;
    asm("mov.b64 %0, {%1, %2};" : "=l"(u) : "f"(lo), "f"(hi));
    return u;
}

__device__ __forceinline__ float2 unpack_f32x2(unsigned long long u) {
    float lo, hi;
    asm("mov.b64 {%0, %1}, %2;" : "=f"(lo), "=f"(hi) : "l"(u));
    return make_float2(lo, hi);
}

// uint4 (8 halves) -> 4 packed f32x2
__device__ __forceinline__ void u4_to_f32x2x4(uint4 u, unsigned long long* f) {
    float2 a = __half22float2(*reinterpret_cast<__half2*>(&u.x));
    float2 b = __half22float2(*reinterpret_cast<__half2*>(&u.y));
    float2 c = __half22float2(*reinterpret_cast<__half2*>(&u.z));
    float2 d = __half22float2(*reinterpret_cast<__half2*>(&u.w));
    f[0] = pack_f32x2(a.x, a.y);
    f[1] = pack_f32x2(b.x, b.y);
    f[2] = pack_f32x2(c.x, c.y);
    f[3] = pack_f32x2(d.x, d.y);
}

// fused mega-prep:
//  warps [0, n):        out[0]=features copy, relu->g_h0 (fp16), layer-0 node dots
//  warps [n, n+r+t):    emb fp16 mirror, norm, u2/u3 for both layers
//  threads [0, e):      edge row counting; rank = atomic return value
__global__ void k_prep(const float* __restrict__ features,
                       float* __restrict__ out,
                       const float* __restrict__ rel,
                       const float* __restrict__ tim,
                       const float* __restrict__ ak,
                       const int* __restrict__ arow,
                       int n, int r, int t, int e) {
    int tid = blockIdx.x * blockDim.x + threadIdx.x;
    if (tid < e) g_rank[tid] = atomicAdd(&g_cnt[arow[tid]], 1);
    int w = tid >> 5, lane = tid & 31;
    if (w < n) {
        float4 v = reinterpret_cast<const float4*>(features)[w * 32 + lane];
        reinterpret_cast<float4*>(out)[w * 32 + lane] = v;   // output[0] = raw features
        v.x = fmaxf(v.x, 0.f); v.y = fmaxf(v.y, 0.f);
        v.z = fmaxf(v.z, 0.f); v.w = fmaxf(v.w, 0.f);
        reinterpret_cast<uint2*>(g_h0)[w * 32 + lane] = pack_half4(v);
        const float* kr = ak;
        const float* kt = ak + 3 * DD;
        float4 a1 = reinterpret_cast<const float4*>(kr)[lane];
        float4 a2 = reinterpret_cast<const float4*>(kr + DD)[lane];
        float4 b1 = reinterpret_cast<const float4*>(kt)[lane];
        float4 b2 = reinterpret_cast<const float4*>(kt + DD)[lane];
        float s1 = wsum(dot4(v, a1));
        float s2 = wsum(dot4(v, a2));
        float s3 = wsum(dot4(v, b1));
        float s4 = wsum(dot4(v, b2));
        if (lane == 0) {
            g_p1r[w] = s1; g_p2r[w] = s2;
            g_p1t[w] = s3; g_p2t[w] = s4;
        }
    } else if (w < n + r + t) {
        int q = w - n;                      // [0, r+t): rel rows first, then time rows
        int isTim = (q >= r) ? 1 : 0;
        const float* src = isTim ? (tim + (size_t)(q - r) * DD)
                                 : (rel + (size_t)q * DD);
        float4 v = reinterpret_cast<const float4*>(src)[lane];
        reinterpret_cast<uint2*>(g_hemb)[q * 32 + lane] = pack_half4(v);
        float nn = wsum(dot4(v, v));
        if (lane == 0) g_nrm[q] = sqrtf(nn);
#pragma unroll
        for (int l = 0; l < 2; l++) {
            const float* kk = ak + (size_t)(l * 2 + isTim) * 3 * DD;
            float4 k2 = reinterpret_cast<const float4*>(kk + DD)[lane];
            float4 k3 = reinterpret_cast<const float4*>(kk + 2 * DD)[lane];
            float u2 = wsum(dot4(v, k2));
            float u3 = wsum(dot4(v, k3));
            if (lane == 0) { g_u2[l][q] = u2; g_u3[l][q] = u3; }
        }
    }
}

// single-launch scan with decoupled lookback (NPART=196 blocks co-resident)
__global__ void k_scan(int n, int e) {
    __shared__ int sh[SCAN_B / 32];
    __shared__ int shoff;
    int tid = threadIdx.x, lane = tid & 31, wid = tid >> 5;
    int bid = blockIdx.x;
    int i = bid * SCAN_B + tid;
    int v = (i < n) ? g_cnt[i] : 0;

    int bs = v;
#pragma unroll
    for (int o = 16; o > 0; o >>= 1) bs += __shfl_down_sync(0xffffffffu, bs, o);
    if (lane == 0) sh[wid] = bs;
    __syncthreads();
    if (tid == 0) {
        int s = 0;
#pragma unroll
        for (int k = 0; k < SCAN_B / 32; k++) s += sh[k];
        atomicExch(&g_part[bid], s + 1);
    }
    __syncthreads();

    int pv = 0;
    if (tid < bid) {
        int x;
        do { x = atomicAdd(&g_part[tid], 0); } while (x == 0);
        pv = x - 1;
    }
    int ps = pv;
#pragma unroll
    for (int o = 16; o > 0; o >>= 1) ps += __shfl_down_sync(0xffffffffu, ps, o);
    if (lane == 0) sh[wid] = ps;
    __syncthreads();
    if (tid == 0) {
        int s = 0;
#pragma unroll
        for (int k = 0; k < SCAN_B / 32; k++) s += sh[k];
        shoff = s;
    }
    __syncthreads();

    int x = v;
#pragma unroll
    for (int o = 1; o < 32; o <<= 1) {
        int y = __shfl_up_sync(0xffffffffu, x, o);
        if (lane >= o) x += y;
    }
    if (lane == 31) sh[wid] = x;
    __syncthreads();
    if (wid == 0) {
        int s = (lane < SCAN_B / 32) ? sh[lane] : 0;
#pragma unroll
        for (int o = 1; o < 32; o <<= 1) {
            int y = __shfl_up_sync(0xffffffffu, s, o);
            if (lane >= o) s += y;
        }
        if (lane < SCAN_B / 32) sh[lane] = s;
    }
    __syncthreads();
    int woff = (wid > 0) ? sh[wid - 1] : 0;
    int excl = x + woff - v + shoff;
    if (i < n) g_rowptr[i] = excl;
    if (i == n - 1) g_rowptr[n] = e;
}

// fused: 16-lane edge scores + atomic-free CSR scatter; restores g_cnt/g_part
__global__ void k_score_scatter(const __half* __restrict__ fh,
                                const int* __restrict__ arow,
                                const int* __restrict__ acol,
                                const int* __restrict__ rcol,
                                const int* __restrict__ tcol,
                                const float* __restrict__ val,
                                int n, int r, int layer, int e) {
    int tid = blockIdx.x * blockDim.x + threadIdx.x;
    if (e > 0) {
        if (tid < n) g_cnt[tid] = 0;
        if (tid < NPART) g_part[tid] = 0;
        if (tid < e) {
            int p = g_rowptr[arow[tid]] + g_rank[tid];
            g_ecol[p] = acol[tid];
        }
    }
    int g = tid >> 4;
    int sl = tid & 15;
    if (g >= n) return;
    int row = arow[g];
    int col = acol[g];
    int rc  = rcol[g];
    int tc  = tcol[g] + r;
    float v = val[g];
    const uint4* fh4 = reinterpret_cast<const uint4*>(fh);
    const uint4* eh4 = reinterpret_cast<const uint4*>(g_hemb);
    uint4 uf = fh4[col * 16 + sl];
    uint4 ur = eh4[rc * 16 + sl];
    uint4 ut = eh4[tc * 16 + sl];
    float dr = dot8h(uf, ur);
    float dt = dot8h(uf, ut);
#pragma unroll
    for (int o = 8; o > 0; o >>= 1) {
        dr += __shfl_down_sync(0xffffffffu, dr, o, 16);
        dt += __shfl_down_sync(0xffffffffu, dt, o, 16);
    }
    if (sl == 0) {
        float cr = v / fmaxf(v * g_nrm[rc], 1e-12f);
        float ct = v / fmaxf(v * g_nrm[tc], 1e-12f);
        float s = g_p1r[row] + g_p2r[col]
                - 2.f * cr * cr * dr * g_u2[layer][rc] + cr * g_u3[layer][rc]
                + g_p1t[row] + g_p2t[col]
                - 2.f * ct * ct * dt * g_u2[layer][tc] + ct * g_u3[layer][tc];
        g_score[g] = s;
    }
}

// one warp per row; TWO edges per iteration via half-warp split:
//  each 16-lane half loads a full fp16 row (uint4/lane), so one LDG.128
//  warp-instruction covers 2 edges. Accumulators: 8 dims/lane (4x f32x2),
//  halves combined once per row via 64-bit shuffles.
__global__ void __launch_bounds__(256, 6)
k_agg(const __half* __restrict__ fh,
      float* __restrict__ out, int n,
      __half* __restrict__ outh,
      const float* __restrict__ nkr,
      const float* __restrict__ nkt) {
    const unsigned FULL = 0xffffffffu;
    int w = (blockIdx.x * blockDim.x + threadIdx.x) >> 5;
    int lane = threadIdx.x & 31;
    if (w >= n) return;
    int beg = g_rowptr[w], end = g_rowptr[w + 1];
    int deg = end - beg;
    int h = lane >> 4;        // half-warp id (edge parity)
    int hl = lane & 15;       // lane within half (dim chunk)

    unsigned long long acc[4];
    acc[0] = acc[1] = acc[2] = acc[3] = pack_f32x2(0.f, 0.f);
    float s;
    const uint4* fh4 = reinterpret_cast<const uint4*>(fh);

    if (deg <= 32) {
        int c = 0;
        float a = -INFINITY;
        if (lane < deg) {
            c = g_ecol[beg + lane];
            a = g_score[c];
        }
        float mm = a;
#pragma unroll
        for (int o = 16; o > 0; o >>= 1)
            mm = fmaxf(mm, __shfl_xor_sync(FULL, mm, o));
        float ex = (lane < deg) ? __expf(a - mm) : 0.f;
        float ss = ex;
#pragma unroll
        for (int o = 16; o > 0; o >>= 1)
            ss += __shfl_xor_sync(FULL, ss, o);
        s = ss;
        int steps = (deg + 1) >> 1;
#pragma unroll 4
        for (int k = 0; k < steps; k++) {
            int eidx = 2 * k + h;                    // < 32 always
            float exk = __shfl_sync(FULL, ex, eidx); // 0 beyond deg
            int   ck  = __shfl_sync(FULL, c, eidx);  // 0 beyond deg (valid row)
            uint4 u = fh4[ck * 16 + hl];
            unsigned long long wk2 = pack_f32x2(exk, exk);
            unsigned long long f[4];
            u4_to_f32x2x4(u, f);
            FMA_F32X2(acc[0], wk2, f[0]);
            FMA_F32X2(acc[1], wk2, f[1]);
            FMA_F32X2(acc[2], wk2, f[2]);
            FMA_F32X2(acc[3], wk2, f[3]);
        }
    } else {
        float mm = -INFINITY;
        for (int j = beg + lane; j < end; j += 32)
            mm = fmaxf(mm, g_score[g_ecol[j]]);
#pragma unroll
        for (int o = 16; o > 0; o >>= 1)
            mm = fmaxf(mm, __shfl_xor_sync(FULL, mm, o));
        s = 0.f;
        for (int base = 0; base < deg; base += 32) {
            int j = beg + base + lane;
            float ex = 0.f;
            int c = 0;
            if (j < end) {
                c = g_ecol[j];
                ex = __expf(g_score[c] - mm);
            }
            float ss = ex;
#pragma unroll
            for (int o = 16; o > 0; o >>= 1)
                ss += __shfl_xor_sync(FULL, ss, o);
            s += ss;
            int lim = min(32, deg - base);
            int steps = (lim + 1) >> 1;
#pragma unroll 4
            for (int k = 0; k < steps; k++) {
                int eidx = 2 * k + h;
                float exk = __shfl_sync(FULL, ex, eidx);
                int   ck  = __shfl_sync(FULL, c, eidx);
                uint4 u = fh4[ck * 16 + hl];
                unsigned long long wk2 = pack_f32x2(exk, exk);
                unsigned long long f[4];
                u4_to_f32x2x4(u, f);
                FMA_F32X2(acc[0], wk2, f[0]);
                FMA_F32X2(acc[1], wk2, f[1]);
                FMA_F32X2(acc[2], wk2, f[2]);
                FMA_F32X2(acc[3], wk2, f[3]);
            }
        }
    }

    // combine the two edge-parity halves: lanes 0-15 += lanes 16-31
#pragma unroll
    for (int i = 0; i < 4; i++) {
        unsigned long long o64 = __shfl_down_sync(FULL, acc[i], 16);
        float2 a = unpack_f32x2(acc[i]);
        float2 b = unpack_f32x2(o64);
        acc[i] = pack_f32x2(a.x + b.x, a.y + b.y);
    }

    float inv = (s > 0.f) ? (1.f / s) : 0.f;
    // lanes 0-15 now own dims [hl*8, hl*8+8)
    float o8[8];
#pragma unroll
    for (int i = 0; i < 4; i++) {
        float2 a = unpack_f32x2(acc[i]);
        o8[2 * i]     = fmaxf(a.x * inv, 0.f);
        o8[2 * i + 1] = fmaxf(a.y * inv, 0.f);
    }
    if (lane < 16) {
        float4 o1 = make_float4(o8[0], o8[1], o8[2], o8[3]);
        float4 o2 = make_float4(o8[4], o8[5], o8[6], o8[7]);
        reinterpret_cast<float4*>(out)[w * 32 + hl * 2]     = o1;
        reinterpret_cast<float4*>(out)[w * 32 + hl * 2 + 1] = o2;
        if (outh) {
            uint2 p1 = pack_half4(o1);
            uint2 p2 = pack_half4(o2);
            uint4 pk = make_uint4(p1.x, p1.y, p2.x, p2.y);
            reinterpret_cast<uint4*>(outh)[w * 16 + hl] = pk;
        }
    }

    if (outh) {   // fused next-layer node dots (lanes 0-15 hold the data)
        float s1 = 0.f, s2 = 0.f, s3 = 0.f, s4 = 0.f;
        if (lane < 16) {
            float4 o1 = make_float4(o8[0], o8[1], o8[2], o8[3]);
            float4 o2 = make_float4(o8[4], o8[5], o8[6], o8[7]);
            float4 ka = reinterpret_cast<const float4*>(nkr)[hl * 2];
            float4 kb = reinterpret_cast<const float4*>(nkr)[hl * 2 + 1];
            s1 = dot4(o1, ka) + dot4(o2, kb);
            ka = reinterpret_cast<const float4*>(nkr + DD)[hl * 2];
            kb = reinterpret_cast<const float4*>(nkr + DD)[hl * 2 + 1];
            s2 = dot4(o1, ka) + dot4(o2, kb);
            ka = reinterpret_cast<const float4*>(nkt)[hl * 2];
            kb = reinterpret_cast<const float4*>(nkt)[hl * 2 + 1];
            s3 = dot4(o1, ka) + dot4(o2, kb);
            ka = reinterpret_cast<const float4*>(nkt + DD)[hl * 2];
            kb = reinterpret_cast<const float4*>(nkt + DD)[hl * 2 + 1];
            s4 = dot4(o1, ka) + dot4(o2, kb);
        }
        s1 = wsum(s1); s2 = wsum(s2); s3 = wsum(s3); s4 = wsum(s4);
        if (lane == 0) {
            g_p1r[w] = s1; g_p2r[w] = s2;
            g_p1t[w] = s3; g_p2t[w] = s4;
        }
    }
}

extern "C" void kernel_launch(void* const* d_in, const int* in_sizes, int n_in,
                              void* d_out, int out_size) {
    const float* features = (const float*)d_in[0];
    const float* rel      = (const float*)d_in[1];
    const float* tim      = (const float*)d_in[2];
    const float* val      = (const float*)d_in[3];
    const float* ak       = (const float*)d_in[4];
    const int*   arow     = (const int*)d_in[5];
    const int*   acol     = (const int*)d_in[6];
    const int*   rcol     = (const int*)d_in[7];
    const int*   tcol     = (const int*)d_in[8];
    float* out = (float*)d_out;

    int n = in_sizes[0] / DD;   // 50000
    int e = in_sizes[5];        // 600000
    int r = in_sizes[1] / DD;   // 1000
    int t = in_sizes[2] / DD;   // 500

    void* h0p = nullptr; cudaGetSymbolAddress(&h0p, g_h0);
    void* h1p = nullptr; cudaGetSymbolAddress(&h1p, g_h1);
    const __half* h0 = (const __half*)h0p;
    __half* h1 = (__half*)h1p;

    int gridN  = (n * 32 + 255) / 256;
    int fusedThreads = max(n * 16, e);
    int gridF = (fusedThreads + 255) / 256;
    int gridN16 = (n * 16 + 255) / 256;

    // 1: fused copy + relu + node dots + emb mirrors/dots + edge counting/ranks
    int prepWarps = n + r + t;
    k_prep<<<(prepWarps * 32 + 255) / 256, 256>>>(features, out, rel, tim, ak,
                                                  arow, n, r, t, e);
    // 2: single-launch lookback scan
    k_scan<<<NPART, SCAN_B>>>(n, e);
    // 3: fused layer-0 scores + CSR scatter (+ state restore)
    k_score_scatter<<<gridF, 256>>>(h0, arow, acol, rcol, tcol, val, n, r, 0, e);
    // 4: layer-0 aggregate (PROFILED SLOT; fuses fp16 mirror + layer-1 node dots)
    k_agg<<<gridN, 256>>>(h0, out + (size_t)n * DD, n, h1,
                          ak + (size_t)2 * 3 * DD, ak + (size_t)3 * 3 * DD);
    // 5-6: layer 1
    k_score_scatter<<<gridN16, 256>>>(h1, arow, acol, rcol, tcol, val, n, r, 1, 0);
    k_agg<<<gridN, 256>>>(h1, out + (size_t)2 * n * DD, n, nullptr, nullptr, nullptr);
}

// round 17
// speedup vs baseline: 1.0647x; 1.0647x over previous
#include <cuda_runtime.h>
#include <cuda_fp16.h>
#include <math.h>

#define NN 50000
#define EE 600000
#define DD 128
#define RR 1000
#define TT 500
#define SCAN_B 256
#define NPART  ((NN + SCAN_B - 1) / SCAN_B)   // 196

// scratch (static device globals — no allocation; zero-initialized at load)
__device__ __half g_h0[NN * DD];                // relu(features), fp16 mirror
__device__ __half g_h1[NN * DD];                // layer-1 features, fp16 mirror
__device__ __half g_hemb[(RR + TT) * DD];       // fp16 mirror of rel|time embeddings
__device__ float g_score[NN];                   // combined edge scores (only first N used)
__device__ float g_p1r[NN], g_p2r[NN], g_p1t[NN], g_p2t[NN];
__device__ float g_nrm[RR + TT];
__device__ float g_u2[2][RR + TT], g_u3[2][RR + TT];
__device__ int   g_cnt[NN];                     // re-zeroed by score_scatter each call
__device__ int   g_rowptr[NN + 1];
__device__ int   g_rank[EE];                    // within-row rank of each edge
__device__ int   g_ecol[EE];                    // acol values in CSR order
__device__ int   g_part[NPART];                 // lookback flags: 0=pending, sum+1=ready

__device__ __forceinline__ float wsum(float v) {
#pragma unroll
    for (int o = 16; o > 0; o >>= 1) v += __shfl_down_sync(0xffffffffu, v, o);
    return v;
}

__device__ __forceinline__ float dot4(float4 a, float4 b) {
    return a.x * b.x + a.y * b.y + a.z * b.z + a.w * b.w;
}

__device__ __forceinline__ uint2 pack_half4(float4 v) {
    __half2 a = __floats2half2_rn(v.x, v.y);
    __half2 b = __floats2half2_rn(v.z, v.w);
    uint2 u;
    u.x = *reinterpret_cast<unsigned*>(&a);
    u.y = *reinterpret_cast<unsigned*>(&b);
    return u;
}

__device__ __forceinline__ float4 unpack_half4(uint2 u) {
    __half2 a = *reinterpret_cast<__half2*>(&u.x);
    __half2 b = *reinterpret_cast<__half2*>(&u.y);
    float2 f1 = __half22float2(a);
    float2 f2 = __half22float2(b);
    return make_float4(f1.x, f1.y, f2.x, f2.y);
}

__device__ __forceinline__ float dot8h(uint4 a, uint4 b) {
    float4 a1 = unpack_half4(make_uint2(a.x, a.y));
    float4 a2 = unpack_half4(make_uint2(a.z, a.w));
    float4 b1 = unpack_half4(make_uint2(b.x, b.y));
    float4 b2 = unpack_half4(make_uint2(b.z, b.w));
    return dot4(a1, b1) + dot4(a2, b2);
}

// packed f32x2 FMA: acc = a * b + acc   (2 fp32 lanes in one instruction)
#define FMA_F32X2(acc, a, b) \
    asm("fma.rn.f32x2 %0, %1, %2, %0;" : "+l"(acc) : "l"(a), "l"(b))

__device__ __forceinline__ unsigned long long pack_f32x2(float lo, float hi) {
    unsigned long long u;
    asm("mov.b64 %0, {%1, %2};" : "=l"(u) : "f"(lo), "f"(hi));
    return u;
}

__device__ __forceinline__ float2 unpack_f32x2(unsigned long long u) {
    float lo, hi;
    asm("mov.b64 {%0, %1}, %2;" : "=f"(lo), "=f"(hi) : "l"(u));
    return make_float2(lo, hi);
}

// half2 pair -> packed f32x2 pair
__device__ __forceinline__ void h4_to_f32x2(uint2 u, unsigned long long& p1,
                                            unsigned long long& p2) {
    float2 f1 = __half22float2(*reinterpret_cast<__half2*>(&u.x));
    float2 f2 = __half22float2(*reinterpret_cast<__half2*>(&u.y));
    p1 = pack_f32x2(f1.x, f1.y);
    p2 = pack_f32x2(f2.x, f2.y);
}

// fused mega-prep:
//  warps [0, n):        out[0]=features copy, relu->g_h0 (fp16), layer-0 node dots
//  warps [n, n+r+t):    emb fp16 mirror, norm, u2/u3 for both layers
//  threads [0, e):      edge row counting; rank = atomic return value
__global__ void k_prep(const float* __restrict__ features,
                       float* __restrict__ out,
                       const float* __restrict__ rel,
                       const float* __restrict__ tim,
                       const float* __restrict__ ak,
                       const int* __restrict__ arow,
                       int n, int r, int t, int e) {
    int tid = blockIdx.x * blockDim.x + threadIdx.x;
    if (tid < e) g_rank[tid] = atomicAdd(&g_cnt[arow[tid]], 1);
    int w = tid >> 5, lane = tid & 31;
    if (w < n) {
        float4 v = reinterpret_cast<const float4*>(features)[w * 32 + lane];
        reinterpret_cast<float4*>(out)[w * 32 + lane] = v;   // output[0] = raw features
        v.x = fmaxf(v.x, 0.f); v.y = fmaxf(v.y, 0.f);
        v.z = fmaxf(v.z, 0.f); v.w = fmaxf(v.w, 0.f);
        reinterpret_cast<uint2*>(g_h0)[w * 32 + lane] = pack_half4(v);
        const float* kr = ak;
        const float* kt = ak + 3 * DD;
        float4 a1 = reinterpret_cast<const float4*>(kr)[lane];
        float4 a2 = reinterpret_cast<const float4*>(kr + DD)[lane];
        float4 b1 = reinterpret_cast<const float4*>(kt)[lane];
        float4 b2 = reinterpret_cast<const float4*>(kt + DD)[lane];
        float s1 = wsum(dot4(v, a1));
        float s2 = wsum(dot4(v, a2));
        float s3 = wsum(dot4(v, b1));
        float s4 = wsum(dot4(v, b2));
        if (lane == 0) {
            g_p1r[w] = s1; g_p2r[w] = s2;
            g_p1t[w] = s3; g_p2t[w] = s4;
        }
    } else if (w < n + r + t) {
        int q = w - n;                      // [0, r+t): rel rows first, then time rows
        int isTim = (q >= r) ? 1 : 0;
        const float* src = isTim ? (tim + (size_t)(q - r) * DD)
                                 : (rel + (size_t)q * DD);
        float4 v = reinterpret_cast<const float4*>(src)[lane];
        reinterpret_cast<uint2*>(g_hemb)[q * 32 + lane] = pack_half4(v);
        float nn = wsum(dot4(v, v));
        if (lane == 0) g_nrm[q] = sqrtf(nn);
#pragma unroll
        for (int l = 0; l < 2; l++) {
            const float* kk = ak + (size_t)(l * 2 + isTim) * 3 * DD;
            float4 k2 = reinterpret_cast<const float4*>(kk + DD)[lane];
            float4 k3 = reinterpret_cast<const float4*>(kk + 2 * DD)[lane];
            float u2 = wsum(dot4(v, k2));
            float u3 = wsum(dot4(v, k3));
            if (lane == 0) { g_u2[l][q] = u2; g_u3[l][q] = u3; }
        }
    }
}

// single-launch scan with decoupled lookback (NPART=196 blocks co-resident)
__global__ void k_scan(int n, int e) {
    __shared__ int sh[SCAN_B / 32];
    __shared__ int shoff;
    int tid = threadIdx.x, lane = tid & 31, wid = tid >> 5;
    int bid = blockIdx.x;
    int i = bid * SCAN_B + tid;
    int v = (i < n) ? g_cnt[i] : 0;

    int bs = v;
#pragma unroll
    for (int o = 16; o > 0; o >>= 1) bs += __shfl_down_sync(0xffffffffu, bs, o);
    if (lane == 0) sh[wid] = bs;
    __syncthreads();
    if (tid == 0) {
        int s = 0;
#pragma unroll
        for (int k = 0; k < SCAN_B / 32; k++) s += sh[k];
        atomicExch(&g_part[bid], s + 1);
    }
    __syncthreads();

    int pv = 0;
    if (tid < bid) {
        int x;
        do { x = atomicAdd(&g_part[tid], 0); } while (x == 0);
        pv = x - 1;
    }
    int ps = pv;
#pragma unroll
    for (int o = 16; o > 0; o >>= 1) ps += __shfl_down_sync(0xffffffffu, ps, o);
    if (lane == 0) sh[wid] = ps;
    __syncthreads();
    if (tid == 0) {
        int s = 0;
#pragma unroll
        for (int k = 0; k < SCAN_B / 32; k++) s += sh[k];
        shoff = s;
    }
    __syncthreads();

    int x = v;
#pragma unroll
    for (int o = 1; o < 32; o <<= 1) {
        int y = __shfl_up_sync(0xffffffffu, x, o);
        if (lane >= o) x += y;
    }
    if (lane == 31) sh[wid] = x;
    __syncthreads();
    if (wid == 0) {
        int s = (lane < SCAN_B / 32) ? sh[lane] : 0;
#pragma unroll
        for (int o = 1; o < 32; o <<= 1) {
            int y = __shfl_up_sync(0xffffffffu, s, o);
            if (lane >= o) s += y;
        }
        if (lane < SCAN_B / 32) sh[lane] = s;
    }
    __syncthreads();
    int woff = (wid > 0) ? sh[wid - 1] : 0;
    int excl = x + woff - v + shoff;
    if (i < n) g_rowptr[i] = excl;
    if (i == n - 1) g_rowptr[n] = e;
}

// fused: 16-lane edge scores + atomic-free CSR scatter; restores g_cnt/g_part
__global__ void __launch_bounds__(256, 8)
k_score_scatter(const __half* __restrict__ fh,
                const int* __restrict__ arow,
                const int* __restrict__ acol,
                const int* __restrict__ rcol,
                const int* __restrict__ tcol,
                const float* __restrict__ val,
                int n, int r, int layer, int e) {
    int tid = blockIdx.x * blockDim.x + threadIdx.x;
    if (e > 0) {
        if (tid < n) g_cnt[tid] = 0;
        if (tid < NPART) g_part[tid] = 0;
        if (tid < e) {
            int p = g_rowptr[arow[tid]] + g_rank[tid];
            g_ecol[p] = acol[tid];
        }
    }
    int g = tid >> 4;
    int sl = tid & 15;
    if (g >= n) return;
    int row = arow[g];
    int col = acol[g];
    int rc  = rcol[g];
    int tc  = tcol[g] + r;
    float v = val[g];
    const uint4* fh4 = reinterpret_cast<const uint4*>(fh);
    const uint4* eh4 = reinterpret_cast<const uint4*>(g_hemb);
    uint4 uf = fh4[col * 16 + sl];
    uint4 ur = eh4[rc * 16 + sl];
    uint4 ut = eh4[tc * 16 + sl];
    float dr = dot8h(uf, ur);
    float dt = dot8h(uf, ut);
#pragma unroll
    for (int o = 8; o > 0; o >>= 1) {
        dr += __shfl_down_sync(0xffffffffu, dr, o, 16);
        dt += __shfl_down_sync(0xffffffffu, dt, o, 16);
    }
    if (sl == 0) {
        float cr = v / fmaxf(v * g_nrm[rc], 1e-12f);
        float ct = v / fmaxf(v * g_nrm[tc], 1e-12f);
        float s = g_p1r[row] + g_p2r[col]
                - 2.f * cr * cr * dr * g_u2[layer][rc] + cr * g_u3[layer][rc]
                + g_p1t[row] + g_p2t[col]
                - 2.f * ct * ct * dt * g_u2[layer][tc] + ct * g_u3[layer][tc];
        g_score[g] = s;
    }
}

// one warp per row; (ex, col) broadcast via register shuffles (no smem staging).
// __launch_bounds__(256, 8) forces <=32 regs -> 64 resident warps/SM.
// (R15 configuration — measured best: 31.4us, occ 82%.)
__global__ void __launch_bounds__(256, 8)
k_agg(const __half* __restrict__ fh,
      float* __restrict__ out, int n,
      __half* __restrict__ outh,
      const float* __restrict__ nkr,
      const float* __restrict__ nkt) {
    const unsigned FULL = 0xffffffffu;
    int w = (blockIdx.x * blockDim.x + threadIdx.x) >> 5;
    int lane = threadIdx.x & 31;
    if (w >= n) return;
    int beg = g_rowptr[w], end = g_rowptr[w + 1];
    int deg = end - beg;

    unsigned long long acc1 = pack_f32x2(0.f, 0.f);
    unsigned long long acc2 = acc1;
    float s;

    if (deg <= 32) {
        int c = 0;
        float a = -INFINITY;
        if (lane < deg) {
            c = g_ecol[beg + lane];
            a = g_score[c];
        }
        float mm = a;
#pragma unroll
        for (int o = 16; o > 0; o >>= 1)
            mm = fmaxf(mm, __shfl_xor_sync(FULL, mm, o));
        float ex = (lane < deg) ? __expf(a - mm) : 0.f;
        float ss = ex;
#pragma unroll
        for (int o = 16; o > 0; o >>= 1)
            ss += __shfl_xor_sync(FULL, ss, o);
        s = ss;
#pragma unroll 4
        for (int k = 0; k < deg; k++) {
            float exk = __shfl_sync(FULL, ex, k);
            int   ck  = __shfl_sync(FULL, c, k);
            unsigned long long wk2 = pack_f32x2(exk, exk);
            uint2 u = reinterpret_cast<const uint2*>(fh)[ck * 32 + lane];
            unsigned long long f1, f2;
            h4_to_f32x2(u, f1, f2);
            FMA_F32X2(acc1, wk2, f1);
            FMA_F32X2(acc2, wk2, f2);
        }
    } else {
        // generic path: global max first, then chunked shuffle-broadcast consume
        float mm = -INFINITY;
        for (int j = beg + lane; j < end; j += 32)
            mm = fmaxf(mm, g_score[g_ecol[j]]);
#pragma unroll
        for (int o = 16; o > 0; o >>= 1)
            mm = fmaxf(mm, __shfl_xor_sync(FULL, mm, o));
        s = 0.f;
        for (int base = 0; base < deg; base += 32) {
            int j = beg + base + lane;
            float ex = 0.f;
            int c = 0;
            if (j < end) {
                c = g_ecol[j];
                ex = __expf(g_score[c] - mm);
            }
            float ss = ex;
#pragma unroll
            for (int o = 16; o > 0; o >>= 1)
                ss += __shfl_xor_sync(FULL, ss, o);
            s += ss;
            int lim = min(32, deg - base);
#pragma unroll 4
            for (int k = 0; k < lim; k++) {
                float exk = __shfl_sync(FULL, ex, k);
                int   ck  = __shfl_sync(FULL, c, k);
                unsigned long long wk2 = pack_f32x2(exk, exk);
                uint2 u = reinterpret_cast<const uint2*>(fh)[ck * 32 + lane];
                unsigned long long f1, f2;
                h4_to_f32x2(u, f1, f2);
                FMA_F32X2(acc1, wk2, f1);
                FMA_F32X2(acc2, wk2, f2);
            }
        }
    }

    float inv = (s > 0.f) ? (1.f / s) : 0.f;
    float2 a1 = unpack_f32x2(acc1);
    float2 a2 = unpack_f32x2(acc2);
    float4 o;
    o.x = fmaxf(a1.x * inv, 0.f);
    o.y = fmaxf(a1.y * inv, 0.f);
    o.z = fmaxf(a2.x * inv, 0.f);
    o.w = fmaxf(a2.y * inv, 0.f);
    reinterpret_cast<float4*>(out)[w * 32 + lane] = o;

    if (outh) {   // fp16 mirror for next layer's gathers + fused next-layer node dots
        reinterpret_cast<uint2*>(outh)[w * 32 + lane] = pack_half4(o);
        float4 k1 = reinterpret_cast<const float4*>(nkr)[lane];
        float4 k2 = reinterpret_cast<const float4*>(nkr + DD)[lane];
        float4 k3 = reinterpret_cast<const float4*>(nkt)[lane];
        float4 k4 = reinterpret_cast<const float4*>(nkt + DD)[lane];
        float s1 = wsum(dot4(o, k1));
        float s2 = wsum(dot4(o, k2));
        float s3 = wsum(dot4(o, k3));
        float s4 = wsum(dot4(o, k4));
        if (lane == 0) {
            g_p1r[w] = s1; g_p2r[w] = s2;
            g_p1t[w] = s3; g_p2t[w] = s4;
        }
    }
}

extern "C" void kernel_launch(void* const* d_in, const int* in_sizes, int n_in,
                              void* d_out, int out_size) {
    const float* features = (const float*)d_in[0];
    const float* rel      = (const float*)d_in[1];
    const float* tim      = (const float*)d_in[2];
    const float* val      = (const float*)d_in[3];
    const float* ak       = (const float*)d_in[4];
    const int*   arow     = (const int*)d_in[5];
    const int*   acol     = (const int*)d_in[6];
    const int*   rcol     = (const int*)d_in[7];
    const int*   tcol     = (const int*)d_in[8];
    float* out = (float*)d_out;

    int n = in_sizes[0] / DD;   // 50000
    int e = in_sizes[5];        // 600000
    int r = in_sizes[1] / DD;   // 1000
    int t = in_sizes[2] / DD;   // 500

    void* h0p = nullptr; cudaGetSymbolAddress(&h0p, g_h0);
    void* h1p = nullptr; cudaGetSymbolAddress(&h1p, g_h1);
    const __half* h0 = (const __half*)h0p;
    __half* h1 = (__half*)h1p;

    int gridN  = (n * 32 + 255) / 256;
    int fusedThreads = max(n * 16, e);
    int gridF = (fusedThreads + 255) / 256;
    int gridN16 = (n * 16 + 255) / 256;

    // 1: fused copy + relu + node dots + emb mirrors/dots + edge counting/ranks
    int prepWarps = n + r + t;
    k_prep<<<(prepWarps * 32 + 255) / 256, 256>>>(features, out, rel, tim, ak,
                                                  arow, n, r, t, e);
    // 2: single-launch lookback scan
    k_scan<<<NPART, SCAN_B>>>(n, e);
    // 3: fused layer-0 scores + CSR scatter (+ state restore)
    k_score_scatter<<<gridF, 256>>>(h0, arow, acol, rcol, tcol, val, n, r, 0, e);
    // 4: layer-0 aggregate (PROFILED SLOT; fuses fp16 mirror + layer-1 node dots)
    k_agg<<<gridN, 256>>>(h0, out + (size_t)n * DD, n, h1,
                          ak + (size_t)2 * 3 * DD, ak + (size_t)3 * 3 * DD);
    // 5-6: layer 1
    k_score_scatter<<<gridN16, 256>>>(h1, arow, acol, rcol, tcol, val, n, r, 1, 0);
    k_agg<<<gridN, 256>>>(h1, out + (size_t)2 * n * DD, n, nullptr, nullptr, nullptr);
}